// round 6
// baseline (speedup 1.0000x reference)
#include <cuda_runtime.h>
#include <cuda_fp16.h>
#include <cstdint>
#include <math.h>

typedef __half half_t;

#define NTOK 16384
#define DM   512
#define DFF  2048
#define SQ   4096
#define NB   4

// ---------------- device scratch (no allocations) ----------------
__device__ half_t g_xh [NTOK * DM];
__device__ half_t g_Wqt[DM * DM];     // [out][in]
__device__ half_t g_Wkt[DM * DM];
__device__ half_t g_Wvt[DM * DM];
__device__ half_t g_W1t[DFF * DM];    // [2048][512]
__device__ half_t g_W2t[DM * DFF];    // [512][2048]
__device__ half_t g_Q  [NTOK * DM];
__device__ half_t g_K  [NTOK * DM];
__device__ half_t g_Vn [NTOK * DM];   // V normal layout
__device__ half_t g_Vt [NB * DM * SQ];// V^T per batch [b][d][tok]
__device__ half_t g_S  [67108864];    // 4*4096*4096, reused as P after softmax
__device__ half_t g_h  [NTOK * DFF];
__device__ half_t g_x1h[NTOK * DM];
__device__ float  g_att[NTOK * DM];   // also ffn output
__device__ float  g_x1 [NTOK * DM];

// ---------------- helpers ----------------
__device__ __forceinline__ uint32_t cvta_smem(const void* p) {
    uint32_t a;
    asm("{ .reg .u64 t; cvta.to.shared.u64 t, %1; cvt.u32.u64 %0, t; }" : "=r"(a) : "l"(p));
    return a;
}
// swizzled byte offset inside a [rows x 32 half] tile (64B rows, 4x16B units)
__device__ __forceinline__ uint32_t swz(int row, int cu) {
    return (uint32_t)(row * 64 + ((cu ^ ((row >> 1) & 3)) << 4));
}
__device__ __forceinline__ void cp_async16(uint32_t dst, const void* src) {
    asm volatile("cp.async.cg.shared.global [%0], [%1], 16;" :: "r"(dst), "l"(src));
}
__device__ __forceinline__ void ldm_x4(uint32_t addr, uint32_t& r0, uint32_t& r1,
                                       uint32_t& r2, uint32_t& r3) {
    asm volatile("ldmatrix.sync.aligned.m8n8.x4.shared.b16 {%0,%1,%2,%3}, [%4];"
                 : "=r"(r0), "=r"(r1), "=r"(r2), "=r"(r3) : "r"(addr));
}
__device__ __forceinline__ void mma16816(float& d0, float& d1, float& d2, float& d3,
                                         uint32_t a0, uint32_t a1, uint32_t a2, uint32_t a3,
                                         uint32_t b0, uint32_t b1) {
    asm volatile("mma.sync.aligned.m16n8k16.row.col.f32.f16.f16.f32 "
                 "{%0,%1,%2,%3}, {%4,%5,%6,%7}, {%8,%9}, {%0,%1,%2,%3};"
                 : "+f"(d0), "+f"(d1), "+f"(d2), "+f"(d3)
                 : "r"(a0), "r"(a1), "r"(a2), "r"(a3), "r"(b0), "r"(b1));
}

// ---------------- fp16 HMMA GEMM: C = alpha * A[M,K] * B[N,K]^T (+bias)(relu) ----------------
// WN: warp N-extent (32 -> BN=128, occ2, 3 stages; 64 -> BN=256, occ1, 4 stages)
// OUT: 0 = fp32, 1 = fp16.  M mult of 128, N mult of BN, K mult of 32.
template<int WN, int OUT, bool BIAS, bool RELU>
__global__ __launch_bounds__(256, (WN == 32) ? 2 : 1)
void hgemm(const half_t* __restrict__ A, const half_t* __restrict__ B,
           const float* __restrict__ bias, void* __restrict__ Cv,
           int M, int N, int K, float alpha,
           long long sA, long long sB, long long sC)
{
    constexpr int BN = 4 * WN;                  // 128 or 256
    constexpr int NT = WN / 8;                  // n fragments (4 or 8)
    constexpr int NP = WN / 16;                 // B ldsm.x4 per ks (2 or 4)
    constexpr int NSTAGE = (WN == 32) ? 3 : 4;
    constexpr int STB = 8192 + BN * 64;         // stage bytes: A 8KB + B BN*64

    extern __shared__ __align__(16) char smbuf[];
    const uint32_t smBase = cvta_smem(smbuf);

    const int tid  = threadIdx.x;
    const int lane = tid & 31;
    const int warp = tid >> 5;
    const int wm = warp >> 2, wn = warp & 3;    // 2 x 4 warps; warp tile 64 x WN
    const int rowBase = blockIdx.y * 128;
    const int colBase = blockIdx.x * BN;

    A += (long long)blockIdx.z * sA;
    B += (long long)blockIdx.z * sB;

    const int lr = tid >> 2;        // 0..63
    const int lc = tid & 3;         // 0..3
    const uint32_t dRow[4] = { swz(lr, lc), swz(lr + 64, lc),
                               swz(lr + 128, lc), swz(lr + 192, lc) };
    const int kIters = K >> 5;

    float acc[4][NT][4];
    #pragma unroll
    for (int i = 0; i < 4; ++i)
        #pragma unroll
        for (int j = 0; j < NT; ++j)
            #pragma unroll
            for (int r = 0; r < 4; ++r) acc[i][j][r] = 0.f;

    auto issue = [&](int it) {
        if (it < kIters) {
            const int k0 = it << 5;
            const uint32_t sa = smBase + (it % NSTAGE) * STB;
            const uint32_t sb = sa + 8192;
            const half_t* gA = A + (long long)(rowBase + lr) * K + k0 + lc * 8;
            const half_t* gB = B + (long long)(colBase + lr) * K + k0 + lc * 8;
            cp_async16(sa + dRow[0], gA);
            cp_async16(sa + dRow[1], gA + (long long)64 * K);
            #pragma unroll
            for (int i = 0; i < BN / 64; ++i)
                cp_async16(sb + dRow[i], gB + (long long)(i * 64) * K);
        }
        asm volatile("cp.async.commit_group;");
    };

    #pragma unroll
    for (int i = 0; i < NSTAGE - 1; ++i) issue(i);

    // fragment address components
    const int aRow0 = wm * 64 + (lane & 15);
    const int aCuHi = lane >> 4;                         // 0/1
    const int bRow0 = wn * WN + (lane & 7) + ((lane >> 4) << 3);
    const int bCuHi = (lane >> 3) & 1;

    for (int it = 0; it < kIters; ++it) {
        asm volatile("cp.async.wait_group %0;" :: "n"(NSTAGE - 2));
        __syncthreads();
        issue(it + NSTAGE - 1);

        const uint32_t sa = smBase + (it % NSTAGE) * STB;
        const uint32_t sb = sa + 8192;

        #pragma unroll
        for (int ks = 0; ks < 2; ++ks) {
            uint32_t af[4][4], bf[NT][2];
            #pragma unroll
            for (int mt = 0; mt < 4; ++mt)
                ldm_x4(sa + swz(aRow0 + mt * 16, ks * 2 + aCuHi),
                       af[mt][0], af[mt][1], af[mt][2], af[mt][3]);
            #pragma unroll
            for (int np = 0; np < NP; ++np) {
                uint32_t r0, r1, r2, r3;
                ldm_x4(sb + swz(bRow0 + np * 16, ks * 2 + bCuHi), r0, r1, r2, r3);
                bf[np * 2][0] = r0; bf[np * 2][1] = r1;
                bf[np * 2 + 1][0] = r2; bf[np * 2 + 1][1] = r3;
            }
            #pragma unroll
            for (int mt = 0; mt < 4; ++mt)
                #pragma unroll
                for (int nt = 0; nt < NT; ++nt)
                    mma16816(acc[mt][nt][0], acc[mt][nt][1], acc[mt][nt][2], acc[mt][nt][3],
                             af[mt][0], af[mt][1], af[mt][2], af[mt][3],
                             bf[nt][0], bf[nt][1]);
        }
        __syncthreads();
    }

    // epilogue
    const long long cz = (long long)blockIdx.z * sC;
    #pragma unroll
    for (int mt = 0; mt < 4; ++mt) {
        const int rA = rowBase + wm * 64 + mt * 16 + (lane >> 2);
        #pragma unroll
        for (int nt = 0; nt < NT; ++nt) {
            const int cc = colBase + wn * WN + nt * 8 + 2 * (lane & 3);
            float v0 = acc[mt][nt][0] * alpha, v1 = acc[mt][nt][1] * alpha;
            float v2 = acc[mt][nt][2] * alpha, v3 = acc[mt][nt][3] * alpha;
            if (BIAS) {
                float2 bv = *(const float2*)(bias + cc);
                v0 += bv.x; v1 += bv.y; v2 += bv.x; v3 += bv.y;
            }
            if (RELU) {
                v0 = fmaxf(v0, 0.f); v1 = fmaxf(v1, 0.f);
                v2 = fmaxf(v2, 0.f); v3 = fmaxf(v3, 0.f);
            }
            if (OUT == 1) {
                half_t* C = (half_t*)Cv;
                *(half2*)(C + cz + (long long)rA * N + cc)       = __floats2half2_rn(v0, v1);
                *(half2*)(C + cz + (long long)(rA + 8) * N + cc) = __floats2half2_rn(v2, v3);
            } else {
                float* C = (float*)Cv;
                *(float2*)(C + cz + (long long)rA * N + cc)       = make_float2(v0, v1);
                *(float2*)(C + cz + (long long)(rA + 8) * N + cc) = make_float2(v2, v3);
            }
        }
    }
}

// ---------------- fp32 -> fp16 convert ----------------
__global__ __launch_bounds__(256)
void cvt_half(const float* __restrict__ in, half_t* __restrict__ out, int n4)
{
    int i = blockIdx.x * 256 + threadIdx.x;
    if (i >= n4) return;
    float4 v = ((const float4*)in)[i];
    union { uint2 u; half_t h[4]; } o;
    o.h[0] = __float2half_rn(v.x); o.h[1] = __float2half_rn(v.y);
    o.h[2] = __float2half_rn(v.z); o.h[3] = __float2half_rn(v.w);
    ((uint2*)out)[i] = o.u;
}

// ---------------- transpose + convert: W[K,N] fp32 -> Wt[N,K] fp16 ----------------
__global__ __launch_bounds__(256)
void transpose_cvt(const float* __restrict__ W, half_t* __restrict__ Wt, int K, int N)
{
    __shared__ float t[32][33];
    int kb = blockIdx.y * 32, nb = blockIdx.x * 32;
    int tx = threadIdx.x, ty = threadIdx.y;  // (32,8)
    #pragma unroll
    for (int i = 0; i < 32; i += 8)
        t[ty + i][tx] = W[(size_t)(kb + ty + i) * N + nb + tx];
    __syncthreads();
    #pragma unroll
    for (int i = 0; i < 32; i += 8)
        Wt[(size_t)(nb + ty + i) * K + kb + tx] = __float2half_rn(t[tx][ty + i]);
}

// ---------------- V transpose: fp16 [16384,512] -> [b][512][4096] ----------------
__global__ __launch_bounds__(256)
void transposeV(const half_t* __restrict__ V, half_t* __restrict__ Vt)
{
    __shared__ half_t t[32][33];
    int dB = blockIdx.x * 32, tokB = blockIdx.y * 32;
    int tx = threadIdx.x, ty = threadIdx.y;  // (32,8)
    #pragma unroll
    for (int i = 0; i < 32; i += 8)
        t[ty + i][tx] = V[(size_t)(tokB + ty + i) * DM + dB + tx];
    __syncthreads();
    const int b = tokB >> 12;
    const int tokin = tokB & (SQ - 1);
    #pragma unroll
    for (int i = 0; i < 32; i += 8)
        Vt[(size_t)b * DM * SQ + (size_t)(dB + ty + i) * SQ + tokin + tx] = t[tx][ty + i];
}

// ---------------- softmax over 4096, fp16 in-place ----------------
__global__ __launch_bounds__(256)
void softmax_h(half_t* __restrict__ S)
{
    half_t* p = S + (long long)blockIdx.x * SQ;
    const int tid = threadIdx.x;
    union U { uint4 q; half_t h[8]; };
    U u[2];
    u[0].q = ((const uint4*)p)[tid];
    u[1].q = ((const uint4*)p)[tid + 256];

    float f[16];
    float mx = -1e30f;
    #pragma unroll
    for (int i = 0; i < 16; ++i) {
        f[i] = __half2float(u[i >> 3].h[i & 7]);
        mx = fmaxf(mx, f[i]);
    }
    __shared__ float sh[8];
    #pragma unroll
    for (int o = 16; o > 0; o >>= 1) mx = fmaxf(mx, __shfl_xor_sync(~0u, mx, o));
    if ((tid & 31) == 0) sh[tid >> 5] = mx;
    __syncthreads();
    mx = sh[0];
    #pragma unroll
    for (int w = 1; w < 8; ++w) mx = fmaxf(mx, sh[w]);
    __syncthreads();

    float sum = 0.f;
    #pragma unroll
    for (int i = 0; i < 16; ++i) { f[i] = __expf(f[i] - mx); sum += f[i]; }
    #pragma unroll
    for (int o = 16; o > 0; o >>= 1) sum += __shfl_xor_sync(~0u, sum, o);
    if ((tid & 31) == 0) sh[tid >> 5] = sum;
    __syncthreads();
    sum = 0.f;
    #pragma unroll
    for (int w = 0; w < 8; ++w) sum += sh[w];
    const float inv = 1.f / sum;

    #pragma unroll
    for (int i = 0; i < 16; ++i)
        u[i >> 3].h[i & 7] = __float2half_rn(f[i] * inv);
    ((uint4*)p)[tid]       = u[0].q;
    ((uint4*)p)[tid + 256] = u[1].q;
}

// ---------------- residual add + LayerNorm(512) ----------------
template<bool EMIT_HALF>
__global__ __launch_bounds__(128)
void add_ln512(const float* __restrict__ X, const float* __restrict__ R,
               const float* __restrict__ g, const float* __restrict__ b,
               float* __restrict__ Y, half_t* __restrict__ Yh)
{
    const int tid = threadIdx.x;
    const long long base = (long long)blockIdx.x * DM;
    float4 v = *(const float4*)(X + base + tid * 4);
    float4 r = *(const float4*)(R + base + tid * 4);
    v.x += r.x; v.y += r.y; v.z += r.z; v.w += r.w;

    __shared__ float shm[4], shv[4];
    float s = v.x + v.y + v.z + v.w;
    #pragma unroll
    for (int o = 16; o > 0; o >>= 1) s += __shfl_xor_sync(~0u, s, o);
    if ((tid & 31) == 0) shm[tid >> 5] = s;
    __syncthreads();
    float mu = (shm[0] + shm[1] + shm[2] + shm[3]) * (1.f / DM);

    float dx = v.x - mu, dy = v.y - mu, dz = v.z - mu, dw = v.w - mu;
    float sq = dx * dx + dy * dy + dz * dz + dw * dw;
    #pragma unroll
    for (int o = 16; o > 0; o >>= 1) sq += __shfl_xor_sync(~0u, sq, o);
    if ((tid & 31) == 0) shv[tid >> 5] = sq;
    __syncthreads();
    float var = (shv[0] + shv[1] + shv[2] + shv[3]) * (1.f / DM);
    float rstd = rsqrtf(var + 1e-5f);

    float4 gg = *(const float4*)(g + tid * 4);
    float4 bb = *(const float4*)(b + tid * 4);
    float4 o;
    o.x = dx * rstd * gg.x + bb.x;
    o.y = dy * rstd * gg.y + bb.y;
    o.z = dz * rstd * gg.z + bb.z;
    o.w = dw * rstd * gg.w + bb.w;
    *(float4*)(Y + base + tid * 4) = o;
    if (EMIT_HALF) {
        union { uint2 u; half_t h[4]; } H;
        H.h[0] = __float2half_rn(o.x); H.h[1] = __float2half_rn(o.y);
        H.h[2] = __float2half_rn(o.z); H.h[3] = __float2half_rn(o.w);
        ((uint2*)(Yh + base))[tid] = H.u;
    }
}

// ---------------- launch ----------------
extern "C" void kernel_launch(void* const* d_in, const int* in_sizes, int n_in,
                              void* d_out, int out_size)
{
    const float* x   = (const float*)d_in[0];
    const float* Wq  = (const float*)d_in[1];
    const float* bq  = (const float*)d_in[2];
    const float* Wk  = (const float*)d_in[3];
    const float* bk  = (const float*)d_in[4];
    const float* Wv  = (const float*)d_in[5];
    const float* bv  = (const float*)d_in[6];
    const float* g1  = (const float*)d_in[7];
    const float* b1  = (const float*)d_in[8];
    const float* g2  = (const float*)d_in[9];
    const float* b2  = (const float*)d_in[10];
    const float* W1  = (const float*)d_in[11];
    const float* bf1 = (const float*)d_in[12];
    const float* W2  = (const float*)d_in[13];
    const float* bf2 = (const float*)d_in[14];
    float* out = (float*)d_out;

    half_t *xh, *Wqt, *Wkt, *Wvt, *W1t, *W2t, *Q, *K, *Vn, *Vt, *S, *h, *x1h;
    float *att, *x1;
    cudaGetSymbolAddress((void**)&xh,  g_xh);
    cudaGetSymbolAddress((void**)&Wqt, g_Wqt);
    cudaGetSymbolAddress((void**)&Wkt, g_Wkt);
    cudaGetSymbolAddress((void**)&Wvt, g_Wvt);
    cudaGetSymbolAddress((void**)&W1t, g_W1t);
    cudaGetSymbolAddress((void**)&W2t, g_W2t);
    cudaGetSymbolAddress((void**)&Q,   g_Q);
    cudaGetSymbolAddress((void**)&K,   g_K);
    cudaGetSymbolAddress((void**)&Vn,  g_Vn);
    cudaGetSymbolAddress((void**)&Vt,  g_Vt);
    cudaGetSymbolAddress((void**)&S,   g_S);
    cudaGetSymbolAddress((void**)&h,   g_h);
    cudaGetSymbolAddress((void**)&x1h, g_x1h);
    cudaGetSymbolAddress((void**)&att, g_att);
    cudaGetSymbolAddress((void**)&x1,  g_x1);

    const int SM128 = 3 * (8192 + 128 * 64);   // 49152
    const int SM256 = 4 * (8192 + 256 * 64);   // 98304
    cudaFuncSetAttribute(hgemm<32, 1, true,  false>, cudaFuncAttributeMaxDynamicSharedMemorySize, SM128);
    cudaFuncSetAttribute(hgemm<32, 0, false, false>, cudaFuncAttributeMaxDynamicSharedMemorySize, SM128);
    cudaFuncSetAttribute(hgemm<32, 0, true,  false>, cudaFuncAttributeMaxDynamicSharedMemorySize, SM128);
    cudaFuncSetAttribute(hgemm<64, 1, false, false>, cudaFuncAttributeMaxDynamicSharedMemorySize, SM256);
    cudaFuncSetAttribute(hgemm<64, 1, true,  true >, cudaFuncAttributeMaxDynamicSharedMemorySize, SM256);

    const float scale = 0.044194173824159216f;  // 1/sqrt(512)
    dim3 tb(32, 8);

    // 0) conversions
    cvt_half<<<(NTOK * DM / 4 + 255) / 256, 256>>>(x, xh, NTOK * DM / 4);
    transpose_cvt<<<dim3(DM / 32, DM / 32),  tb>>>(Wq, Wqt, DM, DM);
    transpose_cvt<<<dim3(DM / 32, DM / 32),  tb>>>(Wk, Wkt, DM, DM);
    transpose_cvt<<<dim3(DM / 32, DM / 32),  tb>>>(Wv, Wvt, DM, DM);
    transpose_cvt<<<dim3(DFF / 32, DM / 32), tb>>>(W1, W1t, DM, DFF);
    transpose_cvt<<<dim3(DM / 32, DFF / 32), tb>>>(W2, W2t, DFF, DM);

    // 1) QKV projections (N=512 -> 128-wide tiles, occ2)
    dim3 gProj(DM / 128, NTOK / 128, 1);
    hgemm<32, 1, true, false><<<gProj, 256, SM128>>>(xh, Wqt, bq, Q,  NTOK, DM, DM, 1.f, 0, 0, 0);
    hgemm<32, 1, true, false><<<gProj, 256, SM128>>>(xh, Wkt, bk, K,  NTOK, DM, DM, 1.f, 0, 0, 0);
    hgemm<32, 1, true, false><<<gProj, 256, SM128>>>(xh, Wvt, bv, Vn, NTOK, DM, DM, 1.f, 0, 0, 0);
    transposeV<<<dim3(DM / 32, NTOK / 32), tb>>>(Vn, Vt);

    // 2) scores = scale * Q K^T (fp16 out), batched, 256-wide tiles
    dim3 gScore(SQ / 256, SQ / 128, NB);
    hgemm<64, 1, false, false><<<gScore, 256, SM256>>>(Q, K, nullptr, S, SQ, SQ, DM, scale,
        (long long)SQ * DM, (long long)SQ * DM, (long long)SQ * SQ);

    // 3) softmax in place (S -> P)
    softmax_h<<<NTOK, 256>>>(S);

    // 4) att = P V (fp32 out), batched (N=512 -> 128-wide)
    dim3 gPV(DM / 128, SQ / 128, NB);
    hgemm<32, 0, false, false><<<gPV, 256, SM128>>>(S, Vt, nullptr, att, SQ, DM, SQ, 1.f,
        (long long)SQ * SQ, (long long)DM * SQ, (long long)SQ * DM);

    // 5) x1 = LN(x + att), emit fp16
    add_ln512<true><<<NTOK, 128>>>(x, att, g1, b1, x1, x1h);

    // 6) h = relu(x1 W1 + bf1) fp16, 256-wide tiles
    dim3 gF1(DFF / 256, NTOK / 128, 1);
    hgemm<64, 1, true, true><<<gF1, 256, SM256>>>(x1h, W1t, bf1, h, NTOK, DFF, DM, 1.f, 0, 0, 0);

    // 7) ffn = h W2 + bf2 fp32 (reuse att), N=512 -> 128-wide
    dim3 gF2(DM / 128, NTOK / 128, 1);
    hgemm<32, 0, true, false><<<gF2, 256, SM128>>>(h, W2t, bf2, att, NTOK, DM, DFF, 1.f, 0, 0, 0);

    // 8) out = LN(x1 + ffn)
    add_ln512<false><<<NTOK, 128>>>(x1, att, g2, b2, out, nullptr);
}

// round 9
// speedup vs baseline: 1.1142x; 1.1142x over previous
#include <cuda_runtime.h>
#include <cuda_fp16.h>
#include <cstdint>
#include <math.h>

typedef __half half_t;

#define NTOK 16384
#define DM   512
#define DFF  2048
#define SQ   4096
#define NB   4

// ---------------- device scratch (no allocations) ----------------
__device__ half_t g_xh   [NTOK * DM];
__device__ half_t g_Wqkvt[3 * DM * DM];   // packed [q|k|v], each [out][in]
__device__ float  g_bqkv [3 * DM];        // packed biases
__device__ half_t g_W1t  [DFF * DM];      // [2048][512]
__device__ half_t g_W2t  [DM * DFF];      // [512][2048]
__device__ half_t g_QKV  [3 * NTOK * DM]; // Q | K | V outputs
__device__ half_t g_Vt   [NB * DM * SQ];  // V^T per batch [b][d][tok]
__device__ half_t g_S    [67108864];      // 4*4096*4096, reused as P after softmax
__device__ half_t g_h    [NTOK * DFF];
__device__ half_t g_x1h  [NTOK * DM];
__device__ float  g_att  [NTOK * DM];     // also ffn output
__device__ float  g_x1   [NTOK * DM];

// ---------------- helpers ----------------
__device__ __forceinline__ uint32_t cvta_smem(const void* p) {
    uint32_t a;
    asm("{ .reg .u64 t; cvta.to.shared.u64 t, %1; cvt.u32.u64 %0, t; }" : "=r"(a) : "l"(p));
    return a;
}
// swizzled byte offset inside a [rows x 32 half] tile (64B rows, 4x16B units)
__device__ __forceinline__ uint32_t swz(int row, int cu) {
    return (uint32_t)(row * 64 + ((cu ^ ((row >> 1) & 3)) << 4));
}
__device__ __forceinline__ void cp_async16(uint32_t dst, const void* src) {
    asm volatile("cp.async.cg.shared.global [%0], [%1], 16;" :: "r"(dst), "l"(src));
}
__device__ __forceinline__ void ldm_x4(uint32_t addr, uint32_t& r0, uint32_t& r1,
                                       uint32_t& r2, uint32_t& r3) {
    asm volatile("ldmatrix.sync.aligned.m8n8.x4.shared.b16 {%0,%1,%2,%3}, [%4];"
                 : "=r"(r0), "=r"(r1), "=r"(r2), "=r"(r3) : "r"(addr));
}
__device__ __forceinline__ void mma16816(float& d0, float& d1, float& d2, float& d3,
                                         uint32_t a0, uint32_t a1, uint32_t a2, uint32_t a3,
                                         uint32_t b0, uint32_t b1) {
    asm volatile("mma.sync.aligned.m16n8k16.row.col.f32.f16.f16.f32 "
                 "{%0,%1,%2,%3}, {%4,%5,%6,%7}, {%8,%9}, {%0,%1,%2,%3};"
                 : "+f"(d0), "+f"(d1), "+f"(d2), "+f"(d3)
                 : "r"(a0), "r"(a1), "r"(a2), "r"(a3), "r"(b0), "r"(b1));
}

// ---------------- fp16 HMMA GEMM: C = alpha * A[M,K] * B[N,K]^T (+bias)(relu) ----------------
// CTA tile 128x128, warp tile 64x32, 4-stage cp.async pipeline, occ 2.
// OUT: 0 = fp32, 1 = fp16.  M,N mult of 128, K mult of 32. Batched via blockIdx.z.
#define NSTAGE 4
#define STB    16384              // stage bytes: A 8KB + B 8KB
#define SMTOT  (NSTAGE * STB)     // 65536

template<int OUT, bool BIAS, bool RELU>
__global__ __launch_bounds__(256, 2)
void hgemm(const half_t* __restrict__ A, const half_t* __restrict__ B,
           const float* __restrict__ bias, void* __restrict__ Cv,
           int M, int N, int K, float alpha,
           long long sA, long long sB, long long sC, long long sBias)
{
    extern __shared__ __align__(16) char smbuf[];
    const uint32_t smBase = cvta_smem(smbuf);

    const int tid  = threadIdx.x;
    const int lane = tid & 31;
    const int warp = tid >> 5;
    const int wm = warp >> 2, wn = warp & 3;    // 2 x 4 warps; warp tile 64 x 32
    const int rowBase = blockIdx.y * 128;
    const int colBase = blockIdx.x * 128;

    A += (long long)blockIdx.z * sA;
    B += (long long)blockIdx.z * sB;
    const float* bp = BIAS ? (bias + (long long)blockIdx.z * sBias) : bias;

    const int lr = tid >> 2;        // 0..63
    const int lc = tid & 3;         // 0..3
    const uint32_t d0 = swz(lr, lc), d1 = swz(lr + 64, lc);
    const int kIters = K >> 5;

    float acc[4][4][4];
    #pragma unroll
    for (int i = 0; i < 4; ++i)
        #pragma unroll
        for (int j = 0; j < 4; ++j)
            #pragma unroll
            for (int r = 0; r < 4; ++r) acc[i][j][r] = 0.f;

    auto issue = [&](int it) {
        if (it < kIters) {
            const int k0 = it << 5;
            const uint32_t sa = smBase + (it % NSTAGE) * STB;
            const uint32_t sb = sa + 8192;
            const half_t* gA = A + (long long)(rowBase + lr) * K + k0 + lc * 8;
            const half_t* gB = B + (long long)(colBase + lr) * K + k0 + lc * 8;
            cp_async16(sa + d0, gA);
            cp_async16(sa + d1, gA + (long long)64 * K);
            cp_async16(sb + d0, gB);
            cp_async16(sb + d1, gB + (long long)64 * K);
        }
        asm volatile("cp.async.commit_group;");
    };

    #pragma unroll
    for (int i = 0; i < NSTAGE - 1; ++i) issue(i);

    // fragment address components
    const int aRow0 = wm * 64 + (lane & 15);
    const int aCuHi = lane >> 4;                         // 0/1
    const int bRow0 = wn * 32 + (lane & 7) + ((lane >> 4) << 3);
    const int bCuHi = (lane >> 3) & 1;

    for (int it = 0; it < kIters; ++it) {
        asm volatile("cp.async.wait_group %0;" :: "n"(NSTAGE - 2));
        __syncthreads();                 // single barrier per iteration
        issue(it + NSTAGE - 1);

        const uint32_t sa = smBase + (it % NSTAGE) * STB;
        const uint32_t sb = sa + 8192;

        #pragma unroll
        for (int ks = 0; ks < 2; ++ks) {
            uint32_t af[4][4], bf[4][2];
            #pragma unroll
            for (int mt = 0; mt < 4; ++mt)
                ldm_x4(sa + swz(aRow0 + mt * 16, ks * 2 + aCuHi),
                       af[mt][0], af[mt][1], af[mt][2], af[mt][3]);
            #pragma unroll
            for (int np = 0; np < 2; ++np) {
                uint32_t r0, r1, r2, r3;
                ldm_x4(sb + swz(bRow0 + np * 16, ks * 2 + bCuHi), r0, r1, r2, r3);
                bf[np * 2][0] = r0; bf[np * 2][1] = r1;
                bf[np * 2 + 1][0] = r2; bf[np * 2 + 1][1] = r3;
            }
            #pragma unroll
            for (int mt = 0; mt < 4; ++mt)
                #pragma unroll
                for (int nt = 0; nt < 4; ++nt)
                    mma16816(acc[mt][nt][0], acc[mt][nt][1], acc[mt][nt][2], acc[mt][nt][3],
                             af[mt][0], af[mt][1], af[mt][2], af[mt][3],
                             bf[nt][0], bf[nt][1]);
        }
    }

    // epilogue
    const long long cz = (long long)blockIdx.z * sC;
    #pragma unroll
    for (int mt = 0; mt < 4; ++mt) {
        const int rA = rowBase + wm * 64 + mt * 16 + (lane >> 2);
        #pragma unroll
        for (int nt = 0; nt < 4; ++nt) {
            const int cc = colBase + wn * 32 + nt * 8 + 2 * (lane & 3);
            float v0 = acc[mt][nt][0] * alpha, v1 = acc[mt][nt][1] * alpha;
            float v2 = acc[mt][nt][2] * alpha, v3 = acc[mt][nt][3] * alpha;
            if (BIAS) {
                float2 bv = *(const float2*)(bp + cc);
                v0 += bv.x; v1 += bv.y; v2 += bv.x; v3 += bv.y;
            }
            if (RELU) {
                v0 = fmaxf(v0, 0.f); v1 = fmaxf(v1, 0.f);
                v2 = fmaxf(v2, 0.f); v3 = fmaxf(v3, 0.f);
            }
            if (OUT == 1) {
                half_t* C = (half_t*)Cv;
                *(half2*)(C + cz + (long long)rA * N + cc)       = __floats2half2_rn(v0, v1);
                *(half2*)(C + cz + (long long)(rA + 8) * N + cc) = __floats2half2_rn(v2, v3);
            } else {
                float* C = (float*)Cv;
                *(float2*)(C + cz + (long long)rA * N + cc)       = make_float2(v0, v1);
                *(float2*)(C + cz + (long long)(rA + 8) * N + cc) = make_float2(v2, v3);
            }
        }
    }
}

// ---------------- fp32 -> fp16 convert ----------------
__global__ __launch_bounds__(256)
void cvt_half(const float* __restrict__ in, half_t* __restrict__ out, int n4)
{
    int i = blockIdx.x * 256 + threadIdx.x;
    if (i >= n4) return;
    float4 v = ((const float4*)in)[i];
    union { uint2 u; half_t h[4]; } o;
    o.h[0] = __float2half_rn(v.x); o.h[1] = __float2half_rn(v.y);
    o.h[2] = __float2half_rn(v.z); o.h[3] = __float2half_rn(v.w);
    ((uint2*)out)[i] = o.u;
}

// ---------------- transpose + convert: W[K,N] fp32 -> Wt[N,K] fp16 ----------------
__global__ __launch_bounds__(256)
void transpose_cvt(const float* __restrict__ W, half_t* __restrict__ Wt, int K, int N)
{
    __shared__ float t[32][33];
    int kb = blockIdx.y * 32, nb = blockIdx.x * 32;
    int tx = threadIdx.x, ty = threadIdx.y;  // (32,8)
    #pragma unroll
    for (int i = 0; i < 32; i += 8)
        t[ty + i][tx] = W[(size_t)(kb + ty + i) * N + nb + tx];
    __syncthreads();
    #pragma unroll
    for (int i = 0; i < 32; i += 8)
        Wt[(size_t)(nb + ty + i) * K + kb + tx] = __float2half_rn(t[tx][ty + i]);
}

// ---------------- V transpose: fp16 [16384,512] -> [b][512][4096] ----------------
__global__ __launch_bounds__(256)
void transposeV(const half_t* __restrict__ V, half_t* __restrict__ Vt)
{
    __shared__ half_t t[32][33];
    int dB = blockIdx.x * 32, tokB = blockIdx.y * 32;
    int tx = threadIdx.x, ty = threadIdx.y;  // (32,8)
    #pragma unroll
    for (int i = 0; i < 32; i += 8)
        t[ty + i][tx] = V[(size_t)(tokB + ty + i) * DM + dB + tx];
    __syncthreads();
    const int b = tokB >> 12;
    const int tokin = tokB & (SQ - 1);
    #pragma unroll
    for (int i = 0; i < 32; i += 8)
        Vt[(size_t)b * DM * SQ + (size_t)(dB + ty + i) * SQ + tokin + tx] = t[tx][ty + i];
}

// ---------------- softmax over 4096, fp16 in-place ----------------
__global__ __launch_bounds__(256)
void softmax_h(half_t* __restrict__ S)
{
    half_t* p = S + (long long)blockIdx.x * SQ;
    const int tid = threadIdx.x;
    union U { uint4 q; half_t h[8]; };
    U u[2];
    u[0].q = ((const uint4*)p)[tid];
    u[1].q = ((const uint4*)p)[tid + 256];

    float f[16];
    float mx = -1e30f;
    #pragma unroll
    for (int i = 0; i < 16; ++i) {
        f[i] = __half2float(u[i >> 3].h[i & 7]);
        mx = fmaxf(mx, f[i]);
    }
    __shared__ float sh[8];
    #pragma unroll
    for (int o = 16; o > 0; o >>= 1) mx = fmaxf(mx, __shfl_xor_sync(~0u, mx, o));
    if ((tid & 31) == 0) sh[tid >> 5] = mx;
    __syncthreads();
    mx = sh[0];
    #pragma unroll
    for (int w = 1; w < 8; ++w) mx = fmaxf(mx, sh[w]);
    __syncthreads();

    float sum = 0.f;
    #pragma unroll
    for (int i = 0; i < 16; ++i) { f[i] = __expf(f[i] - mx); sum += f[i]; }
    #pragma unroll
    for (int o = 16; o > 0; o >>= 1) sum += __shfl_xor_sync(~0u, sum, o);
    if ((tid & 31) == 0) sh[tid >> 5] = sum;
    __syncthreads();
    sum = 0.f;
    #pragma unroll
    for (int w = 0; w < 8; ++w) sum += sh[w];
    const float inv = 1.f / sum;

    #pragma unroll
    for (int i = 0; i < 16; ++i)
        u[i >> 3].h[i & 7] = __float2half_rn(f[i] * inv);
    ((uint4*)p)[tid]       = u[0].q;
    ((uint4*)p)[tid + 256] = u[1].q;
}

// ---------------- residual add + LayerNorm(512) ----------------
template<bool EMIT_HALF>
__global__ __launch_bounds__(128)
void add_ln512(const float* __restrict__ X, const float* __restrict__ R,
               const float* __restrict__ g, const float* __restrict__ b,
               float* __restrict__ Y, half_t* __restrict__ Yh)
{
    const int tid = threadIdx.x;
    const long long base = (long long)blockIdx.x * DM;
    float4 v = *(const float4*)(X + base + tid * 4);
    float4 r = *(const float4*)(R + base + tid * 4);
    v.x += r.x; v.y += r.y; v.z += r.z; v.w += r.w;

    __shared__ float shm[4], shv[4];
    float s = v.x + v.y + v.z + v.w;
    #pragma unroll
    for (int o = 16; o > 0; o >>= 1) s += __shfl_xor_sync(~0u, s, o);
    if ((tid & 31) == 0) shm[tid >> 5] = s;
    __syncthreads();
    float mu = (shm[0] + shm[1] + shm[2] + shm[3]) * (1.f / DM);

    float dx = v.x - mu, dy = v.y - mu, dz = v.z - mu, dw = v.w - mu;
    float sq = dx * dx + dy * dy + dz * dz + dw * dw;
    #pragma unroll
    for (int o = 16; o > 0; o >>= 1) sq += __shfl_xor_sync(~0u, sq, o);
    if ((tid & 31) == 0) shv[tid >> 5] = sq;
    __syncthreads();
    float var = (shv[0] + shv[1] + shv[2] + shv[3]) * (1.f / DM);
    float rstd = rsqrtf(var + 1e-5f);

    float4 gg = *(const float4*)(g + tid * 4);
    float4 bb = *(const float4*)(b + tid * 4);
    float4 o;
    o.x = dx * rstd * gg.x + bb.x;
    o.y = dy * rstd * gg.y + bb.y;
    o.z = dz * rstd * gg.z + bb.z;
    o.w = dw * rstd * gg.w + bb.w;
    *(float4*)(Y + base + tid * 4) = o;
    if (EMIT_HALF) {
        union { uint2 u; half_t h[4]; } H;
        H.h[0] = __float2half_rn(o.x); H.h[1] = __float2half_rn(o.y);
        H.h[2] = __float2half_rn(o.z); H.h[3] = __float2half_rn(o.w);
        ((uint2*)(Yh + base))[tid] = H.u;
    }
}

// ---------------- launch ----------------
extern "C" void kernel_launch(void* const* d_in, const int* in_sizes, int n_in,
                              void* d_out, int out_size)
{
    const float* x   = (const float*)d_in[0];
    const float* Wq  = (const float*)d_in[1];
    const float* bq  = (const float*)d_in[2];
    const float* Wk  = (const float*)d_in[3];
    const float* bk  = (const float*)d_in[4];
    const float* Wv  = (const float*)d_in[5];
    const float* bv  = (const float*)d_in[6];
    const float* g1  = (const float*)d_in[7];
    const float* b1  = (const float*)d_in[8];
    const float* g2  = (const float*)d_in[9];
    const float* b2  = (const float*)d_in[10];
    const float* W1  = (const float*)d_in[11];
    const float* bf1 = (const float*)d_in[12];
    const float* W2  = (const float*)d_in[13];
    const float* bf2 = (const float*)d_in[14];
    float* out = (float*)d_out;

    half_t *xh, *Wqkvt, *W1t, *W2t, *QKV, *Vt, *S, *h, *x1h;
    float *bqkv, *att, *x1;
    cudaGetSymbolAddress((void**)&xh,    g_xh);
    cudaGetSymbolAddress((void**)&Wqkvt, g_Wqkvt);
    cudaGetSymbolAddress((void**)&bqkv,  g_bqkv);
    cudaGetSymbolAddress((void**)&W1t,   g_W1t);
    cudaGetSymbolAddress((void**)&W2t,   g_W2t);
    cudaGetSymbolAddress((void**)&QKV,   g_QKV);
    cudaGetSymbolAddress((void**)&Vt,    g_Vt);
    cudaGetSymbolAddress((void**)&S,     g_S);
    cudaGetSymbolAddress((void**)&h,     g_h);
    cudaGetSymbolAddress((void**)&x1h,   g_x1h);
    cudaGetSymbolAddress((void**)&att,   g_att);
    cudaGetSymbolAddress((void**)&x1,    g_x1);

    cudaFuncSetAttribute(hgemm<1, true,  false>, cudaFuncAttributeMaxDynamicSharedMemorySize, SMTOT);
    cudaFuncSetAttribute(hgemm<1, false, false>, cudaFuncAttributeMaxDynamicSharedMemorySize, SMTOT);
    cudaFuncSetAttribute(hgemm<0, false, false>, cudaFuncAttributeMaxDynamicSharedMemorySize, SMTOT);
    cudaFuncSetAttribute(hgemm<1, true,  true >, cudaFuncAttributeMaxDynamicSharedMemorySize, SMTOT);
    cudaFuncSetAttribute(hgemm<0, true,  false>, cudaFuncAttributeMaxDynamicSharedMemorySize, SMTOT);

    const float scale = 0.044194173824159216f;  // 1/sqrt(512)
    dim3 tb(32, 8);

    half_t* Q  = QKV;
    half_t* K  = QKV + (size_t)NTOK * DM;
    half_t* Vn = QKV + (size_t)2 * NTOK * DM;

    // 0) conversions; pack W^T and biases contiguously
    cvt_half<<<(NTOK * DM / 4 + 255) / 256, 256>>>(x, xh, NTOK * DM / 4);
    transpose_cvt<<<dim3(DM / 32, DM / 32),  tb>>>(Wq, Wqkvt,                 DM, DM);
    transpose_cvt<<<dim3(DM / 32, DM / 32),  tb>>>(Wk, Wqkvt + DM * DM,       DM, DM);
    transpose_cvt<<<dim3(DM / 32, DM / 32),  tb>>>(Wv, Wqkvt + 2 * DM * DM,   DM, DM);
    transpose_cvt<<<dim3(DFF / 32, DM / 32), tb>>>(W1, W1t, DM, DFF);
    transpose_cvt<<<dim3(DM / 32, DFF / 32), tb>>>(W2, W2t, DFF, DM);
    cudaMemcpyAsync(bqkv,          bq, DM * sizeof(float), cudaMemcpyDeviceToDevice);
    cudaMemcpyAsync(bqkv + DM,     bk, DM * sizeof(float), cudaMemcpyDeviceToDevice);
    cudaMemcpyAsync(bqkv + 2 * DM, bv, DM * sizeof(float), cudaMemcpyDeviceToDevice);

    // 1) fused QKV projection: one launch, z = q/k/v
    dim3 gProj(DM / 128, NTOK / 128, 3);
    hgemm<1, true, false><<<gProj, 256, SMTOT>>>(xh, Wqkvt, bqkv, QKV,
        NTOK, DM, DM, 1.f, 0, (long long)DM * DM, (long long)NTOK * DM, DM);
    transposeV<<<dim3(DM / 32, NTOK / 32), tb>>>(Vn, Vt);

    // 2) scores = scale * Q K^T (fp16 out), batched
    dim3 gScore(SQ / 128, SQ / 128, NB);
    hgemm<1, false, false><<<gScore, 256, SMTOT>>>(Q, K, nullptr, S, SQ, SQ, DM, scale,
        (long long)SQ * DM, (long long)SQ * DM, (long long)SQ * SQ, 0);

    // 3) softmax in place (S -> P)
    softmax_h<<<NTOK, 256>>>(S);

    // 4) att = P V (fp32 out), batched
    dim3 gPV(DM / 128, SQ / 128, NB);
    hgemm<0, false, false><<<gPV, 256, SMTOT>>>(S, Vt, nullptr, att, SQ, DM, SQ, 1.f,
        (long long)SQ * SQ, (long long)DM * SQ, (long long)SQ * DM, 0);

    // 5) x1 = LN(x + att), emit fp16
    add_ln512<true><<<NTOK, 128>>>(x, att, g1, b1, x1, x1h);

    // 6) h = relu(x1 W1 + bf1) fp16
    dim3 gF1(DFF / 128, NTOK / 128, 1);
    hgemm<1, true, true><<<gF1, 256, SMTOT>>>(x1h, W1t, bf1, h, NTOK, DFF, DM, 1.f, 0, 0, 0, 0);

    // 7) ffn = h W2 + bf2 fp32 (reuse att)
    dim3 gF2(DM / 128, NTOK / 128, 1);
    hgemm<0, true, false><<<gF2, 256, SMTOT>>>(h, W2t, bf2, att, NTOK, DM, DFF, 1.f, 0, 0, 0, 0);

    // 8) out = LN(x1 + ffn)
    add_ln512<false><<<NTOK, 128>>>(x1, att, g2, b2, out, nullptr);
}

// round 13
// speedup vs baseline: 1.1517x; 1.0337x over previous
#include <cuda_runtime.h>
#include <cuda_fp16.h>
#include <cstdint>
#include <math.h>

typedef __half half_t;

#define NTOK 16384
#define DM   512
#define DFF  2048
#define SQ   4096
#define NB   4

// ---------------- device scratch (no allocations) ----------------
__device__ half_t g_xh   [NTOK * DM];
__device__ half_t g_Wqkvt[3 * DM * DM];   // packed [q|k|v], each [out][in]
__device__ float  g_bqkv [3 * DM];        // packed biases
__device__ half_t g_W1t  [DFF * DM];      // [2048][512]
__device__ half_t g_W2t  [DM * DFF];      // [512][2048]
__device__ half_t g_QKV  [3 * NTOK * DM]; // Q | K | V outputs
__device__ half_t g_Vt   [NB * DM * SQ];  // V^T per batch [b][d][tok]
__device__ half_t g_S    [67108864];      // 4*4096*4096: exp(scores) = unnormalized P
__device__ float  g_rsum [NTOK];          // per-row softmax denominators
__device__ half_t g_h    [NTOK * DFF];
__device__ half_t g_x1h  [NTOK * DM];
__device__ float  g_att  [NTOK * DM];     // also ffn output
__device__ float  g_x1   [NTOK * DM];

// ---------------- helpers ----------------
__device__ __forceinline__ uint32_t cvta_smem(const void* p) {
    uint32_t a;
    asm("{ .reg .u64 t; cvta.to.shared.u64 t, %1; cvt.u32.u64 %0, t; }" : "=r"(a) : "l"(p));
    return a;
}
// swizzled byte offset inside a [rows x 32 half] tile (64B rows, 4x16B units)
__device__ __forceinline__ uint32_t swz(int row, int cu) {
    return (uint32_t)(row * 64 + ((cu ^ ((row >> 1) & 3)) << 4));
}
__device__ __forceinline__ void cp_async16(uint32_t dst, const void* src) {
    asm volatile("cp.async.cg.shared.global [%0], [%1], 16;" :: "r"(dst), "l"(src));
}
__device__ __forceinline__ void ldm_x4(uint32_t addr, uint32_t& r0, uint32_t& r1,
                                       uint32_t& r2, uint32_t& r3) {
    asm volatile("ldmatrix.sync.aligned.m8n8.x4.shared.b16 {%0,%1,%2,%3}, [%4];"
                 : "=r"(r0), "=r"(r1), "=r"(r2), "=r"(r3) : "r"(addr));
}
__device__ __forceinline__ void mma16816(float& d0, float& d1, float& d2, float& d3,
                                         uint32_t a0, uint32_t a1, uint32_t a2, uint32_t a3,
                                         uint32_t b0, uint32_t b1) {
    asm volatile("mma.sync.aligned.m16n8k16.row.col.f32.f16.f16.f32 "
                 "{%0,%1,%2,%3}, {%4,%5,%6,%7}, {%8,%9}, {%0,%1,%2,%3};"
                 : "+f"(d0), "+f"(d1), "+f"(d2), "+f"(d3)
                 : "r"(a0), "r"(a1), "r"(a2), "r"(a3), "r"(b0), "r"(b1));
}

// ---------------- fp16 HMMA GEMM: C = alpha * A[M,K] * B[N,K]^T (+bias)(relu) ----------------
// CTA tile 128x128, warp tile 64x32, 4-stage cp.async pipeline, occ 2, one barrier/iter.
// OUT: 0 = fp32, 1 = fp16.  SMODE: 0 none, 1 = exp + rowsum accumulate (scores),
// 2 = scale rows by 1/rowsum (PV).  M,N mult of 128, K mult of 32. Batched via blockIdx.z.
#define NSTAGE 4
#define STB    16384              // stage bytes: A 8KB + B 8KB
#define SMTOT  (NSTAGE * STB)     // 65536

template<int OUT, bool BIAS, bool RELU, int SMODE>
__global__ __launch_bounds__(256, 2)
void hgemm(const half_t* __restrict__ A, const half_t* __restrict__ B,
           const float* __restrict__ bias, float* __restrict__ rowsum,
           void* __restrict__ Cv,
           int M, int N, int K, float alpha,
           long long sA, long long sB, long long sC, long long sBias)
{
    extern __shared__ __align__(16) char smbuf[];
    const uint32_t smBase = cvta_smem(smbuf);

    const int tid  = threadIdx.x;
    const int lane = tid & 31;
    const int warp = tid >> 5;
    const int wm = warp >> 2, wn = warp & 3;    // 2 x 4 warps; warp tile 64 x 32
    const int rowBase = blockIdx.y * 128;
    const int colBase = blockIdx.x * 128;

    A += (long long)blockIdx.z * sA;
    B += (long long)blockIdx.z * sB;
    const float* bp = BIAS ? (bias + (long long)blockIdx.z * sBias) : bias;

    const int lr = tid >> 2;        // 0..63
    const int lc = tid & 3;         // 0..3
    const uint32_t d0 = swz(lr, lc), d1 = swz(lr + 64, lc);
    const int kIters = K >> 5;

    float acc[4][4][4];
    #pragma unroll
    for (int i = 0; i < 4; ++i)
        #pragma unroll
        for (int j = 0; j < 4; ++j)
            #pragma unroll
            for (int r = 0; r < 4; ++r) acc[i][j][r] = 0.f;

    auto issue = [&](int it) {
        if (it < kIters) {
            const int k0 = it << 5;
            const uint32_t sa = smBase + (it % NSTAGE) * STB;
            const uint32_t sb = sa + 8192;
            const half_t* gA = A + (long long)(rowBase + lr) * K + k0 + lc * 8;
            const half_t* gB = B + (long long)(colBase + lr) * K + k0 + lc * 8;
            cp_async16(sa + d0, gA);
            cp_async16(sa + d1, gA + (long long)64 * K);
            cp_async16(sb + d0, gB);
            cp_async16(sb + d1, gB + (long long)64 * K);
        }
        asm volatile("cp.async.commit_group;");
    };

    #pragma unroll
    for (int i = 0; i < NSTAGE - 1; ++i) issue(i);

    // fragment address components
    const int aRow0 = wm * 64 + (lane & 15);
    const int aCuHi = lane >> 4;                         // 0/1
    const int bRow0 = wn * 32 + (lane & 7) + ((lane >> 4) << 3);
    const int bCuHi = (lane >> 3) & 1;

    for (int it = 0; it < kIters; ++it) {
        asm volatile("cp.async.wait_group %0;" :: "n"(NSTAGE - 2));
        __syncthreads();                 // single barrier per iteration
        issue(it + NSTAGE - 1);

        const uint32_t sa = smBase + (it % NSTAGE) * STB;
        const uint32_t sb = sa + 8192;

        #pragma unroll
        for (int ks = 0; ks < 2; ++ks) {
            uint32_t af[4][4], bf[4][2];
            #pragma unroll
            for (int mt = 0; mt < 4; ++mt)
                ldm_x4(sa + swz(aRow0 + mt * 16, ks * 2 + aCuHi),
                       af[mt][0], af[mt][1], af[mt][2], af[mt][3]);
            #pragma unroll
            for (int np = 0; np < 2; ++np) {
                uint32_t r0, r1, r2, r3;
                ldm_x4(sb + swz(bRow0 + np * 16, ks * 2 + bCuHi), r0, r1, r2, r3);
                bf[np * 2][0] = r0; bf[np * 2][1] = r1;
                bf[np * 2 + 1][0] = r2; bf[np * 2 + 1][1] = r3;
            }
            #pragma unroll
            for (int mt = 0; mt < 4; ++mt)
                #pragma unroll
                for (int nt = 0; nt < 4; ++nt)
                    mma16816(acc[mt][nt][0], acc[mt][nt][1], acc[mt][nt][2], acc[mt][nt][3],
                             af[mt][0], af[mt][1], af[mt][2], af[mt][3],
                             bf[nt][0], bf[nt][1]);
        }
    }

    // epilogue
    const long long cz = (long long)blockIdx.z * sC;
    const int rsBase = blockIdx.z * M;          // rowsum index base (per batch slice)
    #pragma unroll
    for (int mt = 0; mt < 4; ++mt) {
        const int rA = rowBase + wm * 64 + mt * 16 + (lane >> 2);
        float inv0 = 1.f, inv1 = 1.f;
        if (SMODE == 2) {
            inv0 = 1.f / rowsum[rsBase + rA];
            inv1 = 1.f / rowsum[rsBase + rA + 8];
        }
        float rs0 = 0.f, rs1 = 0.f;
        #pragma unroll
        for (int nt = 0; nt < 4; ++nt) {
            const int cc = colBase + wn * 32 + nt * 8 + 2 * (lane & 3);
            float v0 = acc[mt][nt][0] * alpha, v1 = acc[mt][nt][1] * alpha;
            float v2 = acc[mt][nt][2] * alpha, v3 = acc[mt][nt][3] * alpha;
            if (BIAS) {
                float2 bv = *(const float2*)(bp + cc);
                v0 += bv.x; v1 += bv.y; v2 += bv.x; v3 += bv.y;
            }
            if (RELU) {
                v0 = fmaxf(v0, 0.f); v1 = fmaxf(v1, 0.f);
                v2 = fmaxf(v2, 0.f); v3 = fmaxf(v3, 0.f);
            }
            if (SMODE == 1) {   // scores: p = exp(s); accumulate row sums
                v0 = __expf(v0); v1 = __expf(v1);
                v2 = __expf(v2); v3 = __expf(v3);
                rs0 += v0 + v1; rs1 += v2 + v3;
            }
            if (SMODE == 2) {   // PV: normalize by softmax denominator
                v0 *= inv0; v1 *= inv0; v2 *= inv1; v3 *= inv1;
            }
            if (OUT == 1) {
                half_t* C = (half_t*)Cv;
                *(half2*)(C + cz + (long long)rA * N + cc)       = __floats2half2_rn(v0, v1);
                *(half2*)(C + cz + (long long)(rA + 8) * N + cc) = __floats2half2_rn(v2, v3);
            } else {
                float* C = (float*)Cv;
                *(float2*)(C + cz + (long long)rA * N + cc)       = make_float2(v0, v1);
                *(float2*)(C + cz + (long long)(rA + 8) * N + cc) = make_float2(v2, v3);
            }
        }
        if (SMODE == 1) {
            // reduce across the 4 lanes covering the same row (lane&3 varies)
            rs0 += __shfl_xor_sync(~0u, rs0, 1);
            rs0 += __shfl_xor_sync(~0u, rs0, 2);
            rs1 += __shfl_xor_sync(~0u, rs1, 1);
            rs1 += __shfl_xor_sync(~0u, rs1, 2);
            if ((lane & 3) == 0) {
                atomicAdd(&rowsum[rsBase + rA], rs0);       // no return use -> REDG
                atomicAdd(&rowsum[rsBase + rA + 8], rs1);
            }
        }
    }
}

// ---------------- fp32 -> fp16 convert ----------------
__global__ __launch_bounds__(256)
void cvt_half(const float* __restrict__ in, half_t* __restrict__ out, int n4)
{
    int i = blockIdx.x * 256 + threadIdx.x;
    if (i >= n4) return;
    float4 v = ((const float4*)in)[i];
    union { uint2 u; half_t h[4]; } o;
    o.h[0] = __float2half_rn(v.x); o.h[1] = __float2half_rn(v.y);
    o.h[2] = __float2half_rn(v.z); o.h[3] = __float2half_rn(v.w);
    ((uint2*)out)[i] = o.u;
}

// ---------------- transpose + convert: W[K,N] fp32 -> Wt[N,K] fp16 ----------------
__global__ __launch_bounds__(256)
void transpose_cvt(const float* __restrict__ W, half_t* __restrict__ Wt, int K, int N)
{
    __shared__ float t[32][33];
    int kb = blockIdx.y * 32, nb = blockIdx.x * 32;
    int tx = threadIdx.x, ty = threadIdx.y;  // (32,8)
    #pragma unroll
    for (int i = 0; i < 32; i += 8)
        t[ty + i][tx] = W[(size_t)(kb + ty + i) * N + nb + tx];
    __syncthreads();
    #pragma unroll
    for (int i = 0; i < 32; i += 8)
        Wt[(size_t)(nb + ty + i) * K + kb + tx] = __float2half_rn(t[tx][ty + i]);
}

// ---------------- V transpose: fp16 [16384,512] -> [b][512][4096] ----------------
__global__ __launch_bounds__(256)
void transposeV(const half_t* __restrict__ V, half_t* __restrict__ Vt)
{
    __shared__ half_t t[32][33];
    int dB = blockIdx.x * 32, tokB = blockIdx.y * 32;
    int tx = threadIdx.x, ty = threadIdx.y;  // (32,8)
    #pragma unroll
    for (int i = 0; i < 32; i += 8)
        t[ty + i][tx] = V[(size_t)(tokB + ty + i) * DM + dB + tx];
    __syncthreads();
    const int b = tokB >> 12;
    const int tokin = tokB & (SQ - 1);
    #pragma unroll
    for (int i = 0; i < 32; i += 8)
        Vt[(size_t)b * DM * SQ + (size_t)(dB + ty + i) * SQ + tokin + tx] = t[tx][ty + i];
}

// ---------------- residual add + LayerNorm(512) ----------------
template<bool EMIT_HALF>
__global__ __launch_bounds__(128)
void add_ln512(const float* __restrict__ X, const float* __restrict__ R,
               const float* __restrict__ g, const float* __restrict__ b,
               float* __restrict__ Y, half_t* __restrict__ Yh)
{
    const int tid = threadIdx.x;
    const long long base = (long long)blockIdx.x * DM;
    float4 v = *(const float4*)(X + base + tid * 4);
    float4 r = *(const float4*)(R + base + tid * 4);
    v.x += r.x; v.y += r.y; v.z += r.z; v.w += r.w;

    __shared__ float shm[4], shv[4];
    float s = v.x + v.y + v.z + v.w;
    #pragma unroll
    for (int o = 16; o > 0; o >>= 1) s += __shfl_xor_sync(~0u, s, o);
    if ((tid & 31) == 0) shm[tid >> 5] = s;
    __syncthreads();
    float mu = (shm[0] + shm[1] + shm[2] + shm[3]) * (1.f / DM);

    float dx = v.x - mu, dy = v.y - mu, dz = v.z - mu, dw = v.w - mu;
    float sq = dx * dx + dy * dy + dz * dz + dw * dw;
    #pragma unroll
    for (int o = 16; o > 0; o >>= 1) sq += __shfl_xor_sync(~0u, sq, o);
    if ((tid & 31) == 0) shv[tid >> 5] = sq;
    __syncthreads();
    float var = (shv[0] + shv[1] + shv[2] + shv[3]) * (1.f / DM);
    float rstd = rsqrtf(var + 1e-5f);

    float4 gg = *(const float4*)(g + tid * 4);
    float4 bb = *(const float4*)(b + tid * 4);
    float4 o;
    o.x = dx * rstd * gg.x + bb.x;
    o.y = dy * rstd * gg.y + bb.y;
    o.z = dz * rstd * gg.z + bb.z;
    o.w = dw * rstd * gg.w + bb.w;
    *(float4*)(Y + base + tid * 4) = o;
    if (EMIT_HALF) {
        union { uint2 u; half_t h[4]; } H;
        H.h[0] = __float2half_rn(o.x); H.h[1] = __float2half_rn(o.y);
        H.h[2] = __float2half_rn(o.z); H.h[3] = __float2half_rn(o.w);
        ((uint2*)(Yh + base))[tid] = H.u;
    }
}

// ---------------- launch ----------------
extern "C" void kernel_launch(void* const* d_in, const int* in_sizes, int n_in,
                              void* d_out, int out_size)
{
    const float* x   = (const float*)d_in[0];
    const float* Wq  = (const float*)d_in[1];
    const float* bq  = (const float*)d_in[2];
    const float* Wk  = (const float*)d_in[3];
    const float* bk  = (const float*)d_in[4];
    const float* Wv  = (const float*)d_in[5];
    const float* bv  = (const float*)d_in[6];
    const float* g1  = (const float*)d_in[7];
    const float* b1  = (const float*)d_in[8];
    const float* g2  = (const float*)d_in[9];
    const float* b2  = (const float*)d_in[10];
    const float* W1  = (const float*)d_in[11];
    const float* bf1 = (const float*)d_in[12];
    const float* W2  = (const float*)d_in[13];
    const float* bf2 = (const float*)d_in[14];
    float* out = (float*)d_out;

    half_t *xh, *Wqkvt, *W1t, *W2t, *QKV, *Vt, *S, *h, *x1h;
    float *bqkv, *rsum, *att, *x1;
    cudaGetSymbolAddress((void**)&xh,    g_xh);
    cudaGetSymbolAddress((void**)&Wqkvt, g_Wqkvt);
    cudaGetSymbolAddress((void**)&bqkv,  g_bqkv);
    cudaGetSymbolAddress((void**)&W1t,   g_W1t);
    cudaGetSymbolAddress((void**)&W2t,   g_W2t);
    cudaGetSymbolAddress((void**)&QKV,   g_QKV);
    cudaGetSymbolAddress((void**)&Vt,    g_Vt);
    cudaGetSymbolAddress((void**)&S,     g_S);
    cudaGetSymbolAddress((void**)&rsum,  g_rsum);
    cudaGetSymbolAddress((void**)&h,     g_h);
    cudaGetSymbolAddress((void**)&x1h,   g_x1h);
    cudaGetSymbolAddress((void**)&att,   g_att);
    cudaGetSymbolAddress((void**)&x1,    g_x1);

    cudaFuncSetAttribute(hgemm<1, true,  false, 0>, cudaFuncAttributeMaxDynamicSharedMemorySize, SMTOT);
    cudaFuncSetAttribute(hgemm<1, false, false, 1>, cudaFuncAttributeMaxDynamicSharedMemorySize, SMTOT);
    cudaFuncSetAttribute(hgemm<0, false, false, 2>, cudaFuncAttributeMaxDynamicSharedMemorySize, SMTOT);
    cudaFuncSetAttribute(hgemm<1, true,  true,  0>, cudaFuncAttributeMaxDynamicSharedMemorySize, SMTOT);
    cudaFuncSetAttribute(hgemm<0, true,  false, 0>, cudaFuncAttributeMaxDynamicSharedMemorySize, SMTOT);

    const float scale = 0.044194173824159216f;  // 1/sqrt(512)
    dim3 tb(32, 8);

    half_t* Q  = QKV;
    half_t* K  = QKV + (size_t)NTOK * DM;
    half_t* Vn = QKV + (size_t)2 * NTOK * DM;

    // 0) conversions; pack W^T and biases contiguously; zero softmax denominators
    cvt_half<<<(NTOK * DM / 4 + 255) / 256, 256>>>(x, xh, NTOK * DM / 4);
    transpose_cvt<<<dim3(DM / 32, DM / 32),  tb>>>(Wq, Wqkvt,                 DM, DM);
    transpose_cvt<<<dim3(DM / 32, DM / 32),  tb>>>(Wk, Wqkvt + DM * DM,       DM, DM);
    transpose_cvt<<<dim3(DM / 32, DM / 32),  tb>>>(Wv, Wqkvt + 2 * DM * DM,   DM, DM);
    transpose_cvt<<<dim3(DFF / 32, DM / 32), tb>>>(W1, W1t, DM, DFF);
    transpose_cvt<<<dim3(DM / 32, DFF / 32), tb>>>(W2, W2t, DFF, DM);
    cudaMemcpyAsync(bqkv,          bq, DM * sizeof(float), cudaMemcpyDeviceToDevice);
    cudaMemcpyAsync(bqkv + DM,     bk, DM * sizeof(float), cudaMemcpyDeviceToDevice);
    cudaMemcpyAsync(bqkv + 2 * DM, bv, DM * sizeof(float), cudaMemcpyDeviceToDevice);
    cudaMemsetAsync(rsum, 0, NTOK * sizeof(float));

    // 1) fused QKV projection: one launch, z = q/k/v
    dim3 gProj(DM / 128, NTOK / 128, 3);
    hgemm<1, true, false, 0><<<gProj, 256, SMTOT>>>(xh, Wqkvt, bqkv, nullptr, QKV,
        NTOK, DM, DM, 1.f, 0, (long long)DM * DM, (long long)NTOK * DM, DM);
    transposeV<<<dim3(DM / 32, NTOK / 32), tb>>>(Vn, Vt);

    // 2) P = exp(scale * Q K^T) (fp16 out) + rowsum accumulation; batched
    dim3 gScore(SQ / 128, SQ / 128, NB);
    hgemm<1, false, false, 1><<<gScore, 256, SMTOT>>>(Q, K, nullptr, rsum, S, SQ, SQ, DM, scale,
        (long long)SQ * DM, (long long)SQ * DM, (long long)SQ * SQ, 0);

    // 3) att = (P V) / rowsum (fp32 out), batched
    dim3 gPV(DM / 128, SQ / 128, NB);
    hgemm<0, false, false, 2><<<gPV, 256, SMTOT>>>(S, Vt, nullptr, rsum, att, SQ, DM, SQ, 1.f,
        (long long)SQ * SQ, (long long)DM * SQ, (long long)SQ * DM, 0);

    // 4) x1 = LN(x + att), emit fp16
    add_ln512<true><<<NTOK, 128>>>(x, att, g1, b1, x1, x1h);

    // 5) h = relu(x1 W1 + bf1) fp16
    dim3 gF1(DFF / 128, NTOK / 128, 1);
    hgemm<1, true, true, 0><<<gF1, 256, SMTOT>>>(x1h, W1t, bf1, nullptr, h, NTOK, DFF, DM, 1.f, 0, 0, 0, 0);

    // 6) ffn = h W2 + bf2 fp32 (reuse att)
    dim3 gF2(DM / 128, NTOK / 128, 1);
    hgemm<0, true, false, 0><<<gF2, 256, SMTOT>>>(h, W2t, bf2, nullptr, att, NTOK, DM, DFF, 1.f, 0, 0, 0, 0);

    // 7) out = LN(x1 + ffn)
    add_ln512<false><<<NTOK, 128>>>(x1, att, g2, b2, out, nullptr);
}

// round 14
// speedup vs baseline: 1.2854x; 1.1161x over previous
#include <cuda_runtime.h>
#include <cuda_fp16.h>
#include <cstdint>
#include <math.h>

typedef __half half_t;

#define NTOK 16384
#define DM   512
#define DFF  2048
#define SQ   4096
#define NB   4

// ---------------- device scratch (no allocations) ----------------
__device__ half_t g_xh   [NTOK * DM];
__device__ half_t g_Wqkvt[3 * DM * DM];   // packed [q|k|v], each [out][in]
__device__ float  g_bqkv [3 * DM];        // packed biases
__device__ half_t g_W1t  [DFF * DM];      // [2048][512]
__device__ half_t g_W2t  [DM * DFF];      // [512][2048]
__device__ half_t g_QKV  [3 * NTOK * DM]; // Q | K | V outputs
__device__ half_t g_Vt   [NB * DM * SQ];  // V^T per batch [b][d][tok]
__device__ half_t g_S    [67108864];      // 4*4096*4096: exp(scores) = unnormalized P
__device__ float  g_rsum [NTOK];          // per-row softmax denominators
__device__ half_t g_h    [NTOK * DFF];
__device__ half_t g_x1h  [NTOK * DM];
__device__ float  g_att  [NTOK * DM];     // also ffn output
__device__ float  g_x1   [NTOK * DM];

// ---------------- helpers ----------------
__device__ __forceinline__ uint32_t cvta_smem(const void* p) {
    uint32_t a;
    asm("{ .reg .u64 t; cvta.to.shared.u64 t, %1; cvt.u32.u64 %0, t; }" : "=r"(a) : "l"(p));
    return a;
}
// swizzled byte offset inside a [rows x 32 half] tile (64B rows, 4x16B units)
__device__ __forceinline__ uint32_t swz(int row, int cu) {
    return (uint32_t)(row * 64 + ((cu ^ ((row >> 1) & 3)) << 4));
}
__device__ __forceinline__ void cp_async16(uint32_t dst, const void* src) {
    asm volatile("cp.async.cg.shared.global [%0], [%1], 16;" :: "r"(dst), "l"(src));
}
__device__ __forceinline__ void ldm_x4(uint32_t addr, uint32_t& r0, uint32_t& r1,
                                       uint32_t& r2, uint32_t& r3) {
    asm volatile("ldmatrix.sync.aligned.m8n8.x4.shared.b16 {%0,%1,%2,%3}, [%4];"
                 : "=r"(r0), "=r"(r1), "=r"(r2), "=r"(r3) : "r"(addr));
}
__device__ __forceinline__ void mma16816(float& d0, float& d1, float& d2, float& d3,
                                         uint32_t a0, uint32_t a1, uint32_t a2, uint32_t a3,
                                         uint32_t b0, uint32_t b1) {
    asm volatile("mma.sync.aligned.m16n8k16.row.col.f32.f16.f16.f32 "
                 "{%0,%1,%2,%3}, {%4,%5,%6,%7}, {%8,%9}, {%0,%1,%2,%3};"
                 : "+f"(d0), "+f"(d1), "+f"(d2), "+f"(d3)
                 : "r"(a0), "r"(a1), "r"(a2), "r"(a3), "r"(b0), "r"(b1));
}

// ---------------- fp16 HMMA GEMM: C = alpha * A[M,K] * B[N,K]^T (+bias)(relu) ----------------
// CTA tile 128x128, 4 warps (128 thr), warp tile 64x64 (2x2 grid), 4-stage cp.async, occ 2.
// Halves smem read redundancy vs 64x32 warps (A 2x + B 2x = 32KB/iter vs 48KB).
// OUT: 0 = fp32, 1 = fp16.  SMODE: 0 none, 1 = exp + rowsum accumulate (scores),
// 2 = scale rows by 1/rowsum (PV).  M,N mult of 128, K mult of 32. Batched via blockIdx.z.
#define NSTAGE 4
#define STB    16384              // stage bytes: A 8KB + B 8KB
#define SMTOT  (NSTAGE * STB)     // 65536

template<int OUT, bool BIAS, bool RELU, int SMODE>
__global__ __launch_bounds__(128, 2)
void hgemm(const half_t* __restrict__ A, const half_t* __restrict__ B,
           const float* __restrict__ bias, float* __restrict__ rowsum,
           void* __restrict__ Cv,
           int M, int N, int K, float alpha,
           long long sA, long long sB, long long sC, long long sBias)
{
    extern __shared__ __align__(16) char smbuf[];
    const uint32_t smBase = cvta_smem(smbuf);

    const int tid  = threadIdx.x;
    const int lane = tid & 31;
    const int warp = tid >> 5;                  // 0..3
    const int wm = warp >> 1, wn = warp & 1;    // 2 x 2 warps; warp tile 64 x 64
    const int rowBase = blockIdx.y * 128;
    const int colBase = blockIdx.x * 128;

    A += (long long)blockIdx.z * sA;
    B += (long long)blockIdx.z * sB;
    const float* bp = BIAS ? (bias + (long long)blockIdx.z * sBias) : bias;

    const int lr = tid >> 2;        // 0..31
    const int lc = tid & 3;         // 0..3
    const uint32_t dRow[4] = { swz(lr, lc), swz(lr + 32, lc),
                               swz(lr + 64, lc), swz(lr + 96, lc) };
    const int kIters = K >> 5;

    float acc[4][8][4];
    #pragma unroll
    for (int i = 0; i < 4; ++i)
        #pragma unroll
        for (int j = 0; j < 8; ++j)
            #pragma unroll
            for (int r = 0; r < 4; ++r) acc[i][j][r] = 0.f;

    auto issue = [&](int it) {
        if (it < kIters) {
            const int k0 = it << 5;
            const uint32_t sa = smBase + (it % NSTAGE) * STB;
            const uint32_t sb = sa + 8192;
            const half_t* gA = A + (long long)(rowBase + lr) * K + k0 + lc * 8;
            const half_t* gB = B + (long long)(colBase + lr) * K + k0 + lc * 8;
            #pragma unroll
            for (int i = 0; i < 4; ++i) {
                cp_async16(sa + dRow[i], gA + (long long)(i * 32) * K);
                cp_async16(sb + dRow[i], gB + (long long)(i * 32) * K);
            }
        }
        asm volatile("cp.async.commit_group;");
    };

    #pragma unroll
    for (int i = 0; i < NSTAGE - 1; ++i) issue(i);

    // fragment address components
    const int aRow0 = wm * 64 + (lane & 15);
    const int aCuHi = lane >> 4;                         // 0/1
    const int bRow0 = wn * 64 + (lane & 7) + ((lane >> 4) << 3);
    const int bCuHi = (lane >> 3) & 1;

    for (int it = 0; it < kIters; ++it) {
        asm volatile("cp.async.wait_group %0;" :: "n"(NSTAGE - 2));
        __syncthreads();                 // single barrier per iteration
        issue(it + NSTAGE - 1);

        const uint32_t sa = smBase + (it % NSTAGE) * STB;
        const uint32_t sb = sa + 8192;

        #pragma unroll
        for (int ks = 0; ks < 2; ++ks) {
            uint32_t af[4][4], bf[8][2];
            #pragma unroll
            for (int mt = 0; mt < 4; ++mt)
                ldm_x4(sa + swz(aRow0 + mt * 16, ks * 2 + aCuHi),
                       af[mt][0], af[mt][1], af[mt][2], af[mt][3]);
            #pragma unroll
            for (int np = 0; np < 4; ++np) {
                uint32_t r0, r1, r2, r3;
                ldm_x4(sb + swz(bRow0 + np * 16, ks * 2 + bCuHi), r0, r1, r2, r3);
                bf[np * 2][0] = r0; bf[np * 2][1] = r1;
                bf[np * 2 + 1][0] = r2; bf[np * 2 + 1][1] = r3;
            }
            #pragma unroll
            for (int mt = 0; mt < 4; ++mt)
                #pragma unroll
                for (int nt = 0; nt < 8; ++nt)
                    mma16816(acc[mt][nt][0], acc[mt][nt][1], acc[mt][nt][2], acc[mt][nt][3],
                             af[mt][0], af[mt][1], af[mt][2], af[mt][3],
                             bf[nt][0], bf[nt][1]);
        }
    }

    // epilogue
    const long long cz = (long long)blockIdx.z * sC;
    const int rsBase = blockIdx.z * M;          // rowsum index base (per batch slice)
    #pragma unroll
    for (int mt = 0; mt < 4; ++mt) {
        const int rA = rowBase + wm * 64 + mt * 16 + (lane >> 2);
        float inv0 = 1.f, inv1 = 1.f;
        if (SMODE == 2) {
            inv0 = 1.f / rowsum[rsBase + rA];
            inv1 = 1.f / rowsum[rsBase + rA + 8];
        }
        float rs0 = 0.f, rs1 = 0.f;
        #pragma unroll
        for (int nt = 0; nt < 8; ++nt) {
            const int cc = colBase + wn * 64 + nt * 8 + 2 * (lane & 3);
            float v0 = acc[mt][nt][0] * alpha, v1 = acc[mt][nt][1] * alpha;
            float v2 = acc[mt][nt][2] * alpha, v3 = acc[mt][nt][3] * alpha;
            if (BIAS) {
                float2 bv = *(const float2*)(bp + cc);
                v0 += bv.x; v1 += bv.y; v2 += bv.x; v3 += bv.y;
            }
            if (RELU) {
                v0 = fmaxf(v0, 0.f); v1 = fmaxf(v1, 0.f);
                v2 = fmaxf(v2, 0.f); v3 = fmaxf(v3, 0.f);
            }
            if (SMODE == 1) {   // scores: p = exp(s); accumulate row sums
                v0 = __expf(v0); v1 = __expf(v1);
                v2 = __expf(v2); v3 = __expf(v3);
                rs0 += v0 + v1; rs1 += v2 + v3;
            }
            if (SMODE == 2) {   // PV: normalize by softmax denominator
                v0 *= inv0; v1 *= inv0; v2 *= inv1; v3 *= inv1;
            }
            if (OUT == 1) {
                half_t* C = (half_t*)Cv;
                *(half2*)(C + cz + (long long)rA * N + cc)       = __floats2half2_rn(v0, v1);
                *(half2*)(C + cz + (long long)(rA + 8) * N + cc) = __floats2half2_rn(v2, v3);
            } else {
                float* C = (float*)Cv;
                *(float2*)(C + cz + (long long)rA * N + cc)       = make_float2(v0, v1);
                *(float2*)(C + cz + (long long)(rA + 8) * N + cc) = make_float2(v2, v3);
            }
        }
        if (SMODE == 1) {
            // reduce across the 4 lanes covering the same row (lane&3 varies)
            rs0 += __shfl_xor_sync(~0u, rs0, 1);
            rs0 += __shfl_xor_sync(~0u, rs0, 2);
            rs1 += __shfl_xor_sync(~0u, rs1, 1);
            rs1 += __shfl_xor_sync(~0u, rs1, 2);
            if ((lane & 3) == 0) {
                atomicAdd(&rowsum[rsBase + rA], rs0);       // no return use -> REDG
                atomicAdd(&rowsum[rsBase + rA + 8], rs1);
            }
        }
    }
}

// ---------------- fp32 -> fp16 convert ----------------
__global__ __launch_bounds__(256)
void cvt_half(const float* __restrict__ in, half_t* __restrict__ out, int n4)
{
    int i = blockIdx.x * 256 + threadIdx.x;
    if (i >= n4) return;
    float4 v = ((const float4*)in)[i];
    union { uint2 u; half_t h[4]; } o;
    o.h[0] = __float2half_rn(v.x); o.h[1] = __float2half_rn(v.y);
    o.h[2] = __float2half_rn(v.z); o.h[3] = __float2half_rn(v.w);
    ((uint2*)out)[i] = o.u;
}

// ---------------- transpose + convert: W[K,N] fp32 -> Wt[N,K] fp16 ----------------
__global__ __launch_bounds__(256)
void transpose_cvt(const float* __restrict__ W, half_t* __restrict__ Wt, int K, int N)
{
    __shared__ float t[32][33];
    int kb = blockIdx.y * 32, nb = blockIdx.x * 32;
    int tx = threadIdx.x, ty = threadIdx.y;  // (32,8)
    #pragma unroll
    for (int i = 0; i < 32; i += 8)
        t[ty + i][tx] = W[(size_t)(kb + ty + i) * N + nb + tx];
    __syncthreads();
    #pragma unroll
    for (int i = 0; i < 32; i += 8)
        Wt[(size_t)(nb + ty + i) * K + kb + tx] = __float2half_rn(t[tx][ty + i]);
}

// ---------------- V transpose: fp16 [16384,512] -> [b][512][4096] ----------------
__global__ __launch_bounds__(256)
void transposeV(const half_t* __restrict__ V, half_t* __restrict__ Vt)
{
    __shared__ half_t t[32][33];
    int dB = blockIdx.x * 32, tokB = blockIdx.y * 32;
    int tx = threadIdx.x, ty = threadIdx.y;  // (32,8)
    #pragma unroll
    for (int i = 0; i < 32; i += 8)
        t[ty + i][tx] = V[(size_t)(tokB + ty + i) * DM + dB + tx];
    __syncthreads();
    const int b = tokB >> 12;
    const int tokin = tokB & (SQ - 1);
    #pragma unroll
    for (int i = 0; i < 32; i += 8)
        Vt[(size_t)b * DM * SQ + (size_t)(dB + ty + i) * SQ + tokin + tx] = t[tx][ty + i];
}

// ---------------- residual add + LayerNorm(512) ----------------
template<bool EMIT_HALF>
__global__ __launch_bounds__(128)
void add_ln512(const float* __restrict__ X, const float* __restrict__ R,
               const float* __restrict__ g, const float* __restrict__ b,
               float* __restrict__ Y, half_t* __restrict__ Yh)
{
    const int tid = threadIdx.x;
    const long long base = (long long)blockIdx.x * DM;
    float4 v = *(const float4*)(X + base + tid * 4);
    float4 r = *(const float4*)(R + base + tid * 4);
    v.x += r.x; v.y += r.y; v.z += r.z; v.w += r.w;

    __shared__ float shm[4], shv[4];
    float s = v.x + v.y + v.z + v.w;
    #pragma unroll
    for (int o = 16; o > 0; o >>= 1) s += __shfl_xor_sync(~0u, s, o);
    if ((tid & 31) == 0) shm[tid >> 5] = s;
    __syncthreads();
    float mu = (shm[0] + shm[1] + shm[2] + shm[3]) * (1.f / DM);

    float dx = v.x - mu, dy = v.y - mu, dz = v.z - mu, dw = v.w - mu;
    float sq = dx * dx + dy * dy + dz * dz + dw * dw;
    #pragma unroll
    for (int o = 16; o > 0; o >>= 1) sq += __shfl_xor_sync(~0u, sq, o);
    if ((tid & 31) == 0) shv[tid >> 5] = sq;
    __syncthreads();
    float var = (shv[0] + shv[1] + shv[2] + shv[3]) * (1.f / DM);
    float rstd = rsqrtf(var + 1e-5f);

    float4 gg = *(const float4*)(g + tid * 4);
    float4 bb = *(const float4*)(b + tid * 4);
    float4 o;
    o.x = dx * rstd * gg.x + bb.x;
    o.y = dy * rstd * gg.y + bb.y;
    o.z = dz * rstd * gg.z + bb.z;
    o.w = dw * rstd * gg.w + bb.w;
    *(float4*)(Y + base + tid * 4) = o;
    if (EMIT_HALF) {
        union { uint2 u; half_t h[4]; } H;
        H.h[0] = __float2half_rn(o.x); H.h[1] = __float2half_rn(o.y);
        H.h[2] = __float2half_rn(o.z); H.h[3] = __float2half_rn(o.w);
        ((uint2*)(Yh + base))[tid] = H.u;
    }
}

// ---------------- launch ----------------
extern "C" void kernel_launch(void* const* d_in, const int* in_sizes, int n_in,
                              void* d_out, int out_size)
{
    const float* x   = (const float*)d_in[0];
    const float* Wq  = (const float*)d_in[1];
    const float* bq  = (const float*)d_in[2];
    const float* Wk  = (const float*)d_in[3];
    const float* bk  = (const float*)d_in[4];
    const float* Wv  = (const float*)d_in[5];
    const float* bv  = (const float*)d_in[6];
    const float* g1  = (const float*)d_in[7];
    const float* b1  = (const float*)d_in[8];
    const float* g2  = (const float*)d_in[9];
    const float* b2  = (const float*)d_in[10];
    const float* W1  = (const float*)d_in[11];
    const float* bf1 = (const float*)d_in[12];
    const float* W2  = (const float*)d_in[13];
    const float* bf2 = (const float*)d_in[14];
    float* out = (float*)d_out;

    half_t *xh, *Wqkvt, *W1t, *W2t, *QKV, *Vt, *S, *h, *x1h;
    float *bqkv, *rsum, *att, *x1;
    cudaGetSymbolAddress((void**)&xh,    g_xh);
    cudaGetSymbolAddress((void**)&Wqkvt, g_Wqkvt);
    cudaGetSymbolAddress((void**)&bqkv,  g_bqkv);
    cudaGetSymbolAddress((void**)&W1t,   g_W1t);
    cudaGetSymbolAddress((void**)&W2t,   g_W2t);
    cudaGetSymbolAddress((void**)&QKV,   g_QKV);
    cudaGetSymbolAddress((void**)&Vt,    g_Vt);
    cudaGetSymbolAddress((void**)&S,     g_S);
    cudaGetSymbolAddress((void**)&rsum,  g_rsum);
    cudaGetSymbolAddress((void**)&h,     g_h);
    cudaGetSymbolAddress((void**)&x1h,   g_x1h);
    cudaGetSymbolAddress((void**)&att,   g_att);
    cudaGetSymbolAddress((void**)&x1,    g_x1);

    cudaFuncSetAttribute(hgemm<1, true,  false, 0>, cudaFuncAttributeMaxDynamicSharedMemorySize, SMTOT);
    cudaFuncSetAttribute(hgemm<1, false, false, 1>, cudaFuncAttributeMaxDynamicSharedMemorySize, SMTOT);
    cudaFuncSetAttribute(hgemm<0, false, false, 2>, cudaFuncAttributeMaxDynamicSharedMemorySize, SMTOT);
    cudaFuncSetAttribute(hgemm<1, true,  true,  0>, cudaFuncAttributeMaxDynamicSharedMemorySize, SMTOT);
    cudaFuncSetAttribute(hgemm<0, true,  false, 0>, cudaFuncAttributeMaxDynamicSharedMemorySize, SMTOT);

    const float scale = 0.044194173824159216f;  // 1/sqrt(512)
    dim3 tb(32, 8);

    half_t* Q  = QKV;
    half_t* K  = QKV + (size_t)NTOK * DM;
    half_t* Vn = QKV + (size_t)2 * NTOK * DM;

    // 0) conversions; pack W^T and biases contiguously; zero softmax denominators
    cvt_half<<<(NTOK * DM / 4 + 255) / 256, 256>>>(x, xh, NTOK * DM / 4);
    transpose_cvt<<<dim3(DM / 32, DM / 32),  tb>>>(Wq, Wqkvt,                 DM, DM);
    transpose_cvt<<<dim3(DM / 32, DM / 32),  tb>>>(Wk, Wqkvt + DM * DM,       DM, DM);
    transpose_cvt<<<dim3(DM / 32, DM / 32),  tb>>>(Wv, Wqkvt + 2 * DM * DM,   DM, DM);
    transpose_cvt<<<dim3(DFF / 32, DM / 32), tb>>>(W1, W1t, DM, DFF);
    transpose_cvt<<<dim3(DM / 32, DFF / 32), tb>>>(W2, W2t, DFF, DM);
    cudaMemcpyAsync(bqkv,          bq, DM * sizeof(float), cudaMemcpyDeviceToDevice);
    cudaMemcpyAsync(bqkv + DM,     bk, DM * sizeof(float), cudaMemcpyDeviceToDevice);
    cudaMemcpyAsync(bqkv + 2 * DM, bv, DM * sizeof(float), cudaMemcpyDeviceToDevice);
    cudaMemsetAsync(rsum, 0, NTOK * sizeof(float));

    // 1) fused QKV projection: one launch, z = q/k/v
    dim3 gProj(DM / 128, NTOK / 128, 3);
    hgemm<1, true, false, 0><<<gProj, 128, SMTOT>>>(xh, Wqkvt, bqkv, nullptr, QKV,
        NTOK, DM, DM, 1.f, 0, (long long)DM * DM, (long long)NTOK * DM, DM);
    transposeV<<<dim3(DM / 32, NTOK / 32), tb>>>(Vn, Vt);

    // 2) P = exp(scale * Q K^T) (fp16 out) + rowsum accumulation; batched
    dim3 gScore(SQ / 128, SQ / 128, NB);
    hgemm<1, false, false, 1><<<gScore, 128, SMTOT>>>(Q, K, nullptr, rsum, S, SQ, SQ, DM, scale,
        (long long)SQ * DM, (long long)SQ * DM, (long long)SQ * SQ, 0);

    // 3) att = (P V) / rowsum (fp32 out), batched
    dim3 gPV(DM / 128, SQ / 128, NB);
    hgemm<0, false, false, 2><<<gPV, 128, SMTOT>>>(S, Vt, nullptr, rsum, att, SQ, DM, SQ, 1.f,
        (long long)SQ * SQ, (long long)DM * SQ, (long long)SQ * DM, 0);

    // 4) x1 = LN(x + att), emit fp16
    add_ln512<true><<<NTOK, 128>>>(x, att, g1, b1, x1, x1h);

    // 5) h = relu(x1 W1 + bf1) fp16
    dim3 gF1(DFF / 128, NTOK / 128, 1);
    hgemm<1, true, true, 0><<<gF1, 128, SMTOT>>>(x1h, W1t, bf1, nullptr, h, NTOK, DFF, DM, 1.f, 0, 0, 0, 0);

    // 6) ffn = h W2 + bf2 fp32 (reuse att)
    dim3 gF2(DM / 128, NTOK / 128, 1);
    hgemm<0, true, false, 0><<<gF2, 128, SMTOT>>>(h, W2t, bf2, nullptr, att, NTOK, DM, DFF, 1.f, 0, 0, 0, 0);

    // 7) out = LN(x1 + ffn)
    add_ln512<false><<<NTOK, 128>>>(x1, att, g2, b2, out, nullptr);
}